// round 13
// baseline (speedup 1.0000x reference)
#include <cuda_runtime.h>
#include <cuda_bf16.h>
#include <mma.h>
#include <cstdint>

using namespace nvcuda;

#define B_DIM 128
#define K_DIM 2048
#define D_DIM 512

// GEMM tiling
#define BM 64               // batch rows per block
#define BN 16               // k cols per block
#define DC 32               // d per pipeline stage
#define NSTAGE (D_DIM / DC) // 16
#define NBUF 6              // cp.async ring depth (5-stage lookahead)
#define PITCH 40            // bf16 per smem row (32 + 8 pad) = 80B, LDSM conflict-free
#define THREADS 256

// per-buffer smem (bf16 elems): XH 64*40, XL 64*40, PH/PL/AH/AL 16*40 each
#define XH_B 0
#define XL_B (64 * PITCH)
#define PH_B (128 * PITCH)
#define PL_B (144 * PITCH)
#define AH_B (160 * PITCH)
#define AL_B (176 * PITCH)
#define BUF_ELEMS (192 * PITCH)            // 7680 bf16 = 15360 B
#define C_OFF (NBUF * BUF_ELEMS * 2)       // 92160 B; f32 C[2048]
#define SMEM_BYTES (C_OFF + 8192)          // 100352 B

// ---------------------------------------------------------------------------
// Device-global scratch (no cudaMalloc allowed)
// ---------------------------------------------------------------------------
__device__ float g_uu[K_DIM];
__device__ float g_ua[K_DIM];
__device__ float g_a2[K_DIM];
__device__ float g_vv[B_DIM];
__device__ __nv_bfloat16 g_ph[K_DIM * D_DIM];
__device__ __nv_bfloat16 g_pl[K_DIM * D_DIM];
__device__ __nv_bfloat16 g_ah[K_DIM * D_DIM];
__device__ __nv_bfloat16 g_al[K_DIM * D_DIM];
__device__ __nv_bfloat16 g_xh[B_DIM * D_DIM];
__device__ __nv_bfloat16 g_xl[B_DIM * D_DIM];

struct __align__(8) bh4 { __nv_bfloat162 a, b; };

__device__ __forceinline__ void split4(float4 v, __nv_bfloat16* hi,
                                       __nv_bfloat16* lo, int idx) {
    __nv_bfloat16 h0 = __float2bfloat16_rn(v.x);
    __nv_bfloat16 h1 = __float2bfloat16_rn(v.y);
    __nv_bfloat16 h2 = __float2bfloat16_rn(v.z);
    __nv_bfloat16 h3 = __float2bfloat16_rn(v.w);
    bh4 H; H.a = __nv_bfloat162(h0, h1); H.b = __nv_bfloat162(h2, h3);
    *(bh4*)(hi + idx) = H;
    bh4 L;
    L.a = __nv_bfloat162(__float2bfloat16_rn(v.x - __bfloat162float(h0)),
                         __float2bfloat16_rn(v.y - __bfloat162float(h1)));
    L.b = __nv_bfloat162(__float2bfloat16_rn(v.z - __bfloat162float(h2)),
                         __float2bfloat16_rn(v.w - __bfloat162float(h3)));
    *(bh4*)(lo + idx) = L;
}

// ---------------------------------------------------------------------------
// Kernel 1: per-row stats (fp32) + bf16 hi/lo split of p, a, x.
// ---------------------------------------------------------------------------
__global__ void stats_split_kernel(const float* __restrict__ inp,
                                   const float* __restrict__ p,
                                   const float* __restrict__ a) {
    int warp = (blockIdx.x * blockDim.x + threadIdx.x) >> 5;
    int lane = threadIdx.x & 31;

    if (warp < K_DIM) {
        const float4* pr = (const float4*)(p + warp * D_DIM);
        const float4* ar = (const float4*)(a + warp * D_DIM);
        float pp = 0.f, pa = 0.f, aa = 0.f;
#pragma unroll
        for (int i = 0; i < D_DIM / 128; i++) {
            float4 pv = pr[lane + i * 32];
            float4 av = ar[lane + i * 32];
            pp += pv.x * pv.x + pv.y * pv.y + pv.z * pv.z + pv.w * pv.w;
            pa += pv.x * av.x + pv.y * av.y + pv.z * av.z + pv.w * av.w;
            aa += av.x * av.x + av.y * av.y + av.z * av.z + av.w * av.w;
            int idx = warp * D_DIM + (lane + i * 32) * 4;
            split4(pv, g_ph, g_pl, idx);
            split4(av, g_ah, g_al, idx);
        }
#pragma unroll
        for (int off = 16; off > 0; off >>= 1) {
            pp += __shfl_xor_sync(0xFFFFFFFFu, pp, off);
            pa += __shfl_xor_sync(0xFFFFFFFFu, pa, off);
            aa += __shfl_xor_sync(0xFFFFFFFFu, aa, off);
        }
        if (lane == 0) {
            g_uu[warp] = pp;
            g_ua[warp] = -pa;
            g_a2[warp] = aa;
        }
    } else if (warp < K_DIM + B_DIM) {
        int b = warp - K_DIM;
        const float4* xr = (const float4*)(inp + b * D_DIM);
        float vv = 0.f;
#pragma unroll
        for (int i = 0; i < D_DIM / 128; i++) {
            float4 xv = xr[lane + i * 32];
            vv += xv.x * xv.x + xv.y * xv.y + xv.z * xv.z + xv.w * xv.w;
            split4(xv, g_xh, g_xl, b * D_DIM + (lane + i * 32) * 4);
        }
#pragma unroll
        for (int off = 16; off > 0; off >>= 1)
            vv += __shfl_xor_sync(0xFFFFFFFFu, vv, off);
        if (lane == 0) g_vv[b] = vv;
    }
}

// cp.async helpers
__device__ __forceinline__ void cp16(void* dst, const void* src) {
    unsigned saddr = (unsigned)__cvta_generic_to_shared(dst);
    asm volatile("cp.async.cg.shared.global [%0], [%1], 16;\n"
                 :: "r"(saddr), "l"(src));
}
__device__ __forceinline__ void cp_commit() {
    asm volatile("cp.async.commit_group;\n" ::: "memory");
}
__device__ __forceinline__ void cp_wait_n(int n) {
    switch (n) {
    case 0: asm volatile("cp.async.wait_group 0;" ::: "memory"); break;
    case 1: asm volatile("cp.async.wait_group 1;" ::: "memory"); break;
    case 2: asm volatile("cp.async.wait_group 2;" ::: "memory"); break;
    case 3: asm volatile("cp.async.wait_group 3;" ::: "memory"); break;
    default: asm volatile("cp.async.wait_group 4;" ::: "memory"); break;
    }
}

// ---------------------------------------------------------------------------
// Kernel 2: bf16 WMMA dual GEMM (3-term fp32-emulation) + MLR epilogue.
// Grid (K/BN, B/BM) = (128, 2) = 256 blocks, 256 threads (8 warps).
// Warps 0-3: P-GEMM rows [16w,16w+16); warps 4-7: A-GEMM same rows.
// 6-buffer cp.async ring over 16 stages of DC=32 — 5-stage lookahead,
// ONE __syncthreads per stage (refill of buffer (t-1)%6 is issued right
// after the entry sync, which already orders it against stage t-1 compute).
// ---------------------------------------------------------------------------
__global__ __launch_bounds__(THREADS, 2)
void hyper_logits_wmma(float* __restrict__ out) {
    extern __shared__ __align__(16) __nv_bfloat16 smb[];
    float* C = (float*)((char*)smb + C_OFF);

    const int tid = threadIdx.x;
    const int warp = tid >> 5;
    const int mat = warp >> 2;          // 0: P-GEMM, 1: A-GEMM
    const int wb = warp & 3;            // b-row group (16 rows each)
    const int kbase = blockIdx.x * BN;
    const int bbase = blockIdx.y * BM;

    // ---- stage copy: 3 cp16 per thread ----
    auto copy_stage = [&](int stg) {
        __nv_bfloat16* buf = smb + (stg % NBUF) * BUF_ELEMS;
        const int d0 = stg * DC;
        {   // X hi + lo: 64 rows x 4 16B-chunks = 256 cp16 each
            int row = tid >> 2, c8 = (tid & 3) * 8;
            size_t g = (size_t)(bbase + row) * D_DIM + d0 + c8;
            int so = row * PITCH + c8;
            cp16(buf + XH_B + so, g_xh + g);
            cp16(buf + XL_B + so, g_xl + g);
        }
        {   // weights: 4 arrays x 16 rows x 4 chunks = 64 cp16 each
            int arr = tid >> 6, r = tid & 63;
            int row = r >> 2, c8 = (r & 3) * 8;
            size_t g = (size_t)(kbase + row) * D_DIM + d0 + c8;
            int so = row * PITCH + c8;
            const __nv_bfloat16* src =
                (arr == 0) ? g_ph : (arr == 1) ? g_pl : (arr == 2) ? g_ah : g_al;
            int dstb = (arr == 0) ? PH_B : (arr == 1) ? PL_B
                     : (arr == 2) ? AH_B : AL_B;
            cp16(buf + dstb + so, src + g);
        }
    };

    wmma::fragment<wmma::accumulator, 16, 16, 16, float> accA, accB;
    wmma::fill_fragment(accA, 0.0f);
    wmma::fill_fragment(accB, 0.0f);

    // prologue: fill 5 buffers
#pragma unroll
    for (int s = 0; s < NBUF - 1; s++) {
        copy_stage(s);
        cp_commit();
    }

    for (int t = 0; t < NSTAGE; t++) {
        // stage t copies complete when <= min(4, NSTAGE-1-t) groups pending
        int rem = NSTAGE - 1 - t;
        cp_wait_n(rem < 4 ? rem : 4);
        __syncthreads();            // data ready + all warps done with t-1

        if (t + NBUF - 1 < NSTAGE) {
            copy_stage(t + NBUF - 1);   // refills buffer (t-1) % NBUF
            cp_commit();
        }

        const __nv_bfloat16* buf = smb + (t % NBUF) * BUF_ELEMS;
        const __nv_bfloat16* xh = buf + XH_B + wb * 16 * PITCH;
        const __nv_bfloat16* xl = buf + XL_B + wb * 16 * PITCH;
        const __nv_bfloat16* bh = buf + (mat ? AH_B : PH_B);
        const __nv_bfloat16* bl = buf + (mat ? AL_B : PL_B);

#pragma unroll
        for (int cc = 0; cc < DC / 16; cc++) {
            const int dcol = cc * 16;
            wmma::fragment<wmma::matrix_a, 16, 16, 16, __nv_bfloat16,
                           wmma::row_major> aH, aL;
            wmma::fragment<wmma::matrix_b, 16, 16, 16, __nv_bfloat16,
                           wmma::col_major> fBH, fBL;
            wmma::load_matrix_sync(aH, xh + dcol, PITCH);
            wmma::load_matrix_sync(aL, xl + dcol, PITCH);
            wmma::load_matrix_sync(fBH, bh + dcol, PITCH);
            wmma::load_matrix_sync(fBL, bl + dcol, PITCH);

            wmma::mma_sync(accA, aH, fBH, accA);
            wmma::mma_sync(accB, aH, fBL, accB);
            wmma::mma_sync(accA, aL, fBH, accA);
        }
    }

    // combine partial accumulators
#pragma unroll
    for (int e = 0; e < accA.num_elements; e++)
        accA.x[e] += accB.x[e];

    __syncthreads();                // all stages done; buffers reusable as C
    wmma::store_matrix_sync(C + mat * 1024 + wb * 256, accA, 16,
                            wmma::mem_row_major);
    __syncthreads();

    // ---- epilogue: 64 rows x 16 cols = 1024 logits, 4 per thread ----
#pragma unroll
    for (int i = 0; i < 4; i++) {
        int idx = tid + 256 * i;                    // 0..1023
        int r = idx >> 4;                           // local b row 0..63
        int c = idx & 15;                           // local k col
        const int b = bbase + r;
        const int k = kbase + c;

        float xp = C[idx];
        float xa = C[1024 + idx];

        const float uu = g_uu[k];
        const float ua = g_ua[k];
        const float an = sqrtf(g_a2[k]);
        const float coef = 2.0f / (1.0f - uu) * an;
        const float beta = 1.0f - uu;
        const float vv = g_vv[b];

        float uv = -xp;                             // <u,x> = -<p,x>
        float alpha = 1.0f + 2.0f * uv + vv;
        float den   = 1.0f + 2.0f * uv + uu * vv;
        float inv   = 1.0f / den;
        float wa = (alpha * ua + beta * xa) * inv;
        float ww = (alpha * alpha * uu + 2.0f * alpha * beta * uv
                    + beta * beta * vv) * (inv * inv);
        out[b * K_DIM + k] = coef * asinhf(2.0f * wa / (an * (1.0f - ww)));
    }
}

// ---------------------------------------------------------------------------
extern "C" void kernel_launch(void* const* d_in, const int* in_sizes, int n_in,
                              void* d_out, int out_size) {
    const float* inp = (const float*)d_in[0];   // [B, D]
    const float* p   = (const float*)d_in[1];   // [K, D]
    const float* a   = (const float*)d_in[2];   // [K, D]
    float* out = (float*)d_out;                 // [B, K]

    static bool attr_set = false;
    if (!attr_set) {
        cudaFuncSetAttribute(hyper_logits_wmma,
                             cudaFuncAttributeMaxDynamicSharedMemorySize,
                             SMEM_BYTES);
        attr_set = true;
    }

    int nwarps = K_DIM + B_DIM;
    int blocks1 = (nwarps * 32 + 255) / 256;
    stats_split_kernel<<<blocks1, 256>>>(inp, p, a);

    dim3 grid(K_DIM / BN, B_DIM / BM);   // (128, 2) = 256 blocks
    hyper_logits_wmma<<<grid, THREADS, SMEM_BYTES>>>(out);
}

// round 14
// speedup vs baseline: 1.1237x; 1.1237x over previous
#include <cuda_runtime.h>
#include <cuda_bf16.h>
#include <mma.h>
#include <cstdint>

using namespace nvcuda;

#define B_DIM 128
#define K_DIM 2048
#define D_DIM 512

// GEMM tiling
#define BM 64                // batch rows per block
#define BN 16                // k cols per block
#define GD 256               // d-range per warpgroup (2 groups cover 512)
#define DCW 32               // d per stage
#define NST (GD / DCW)       // 8 stages per group
#define PITCH 40             // bf16 per smem row (32 + 8 pad) = 80B
#define THREADS 512

// per-buffer layout (bf16 elems)
#define XH_B 0
#define XL_B (64 * PITCH)
#define PH_B (128 * PITCH)
#define PL_B (144 * PITCH)
#define AH_B (160 * PITCH)
#define AL_B (176 * PITCH)
#define BUF_ELEMS (192 * PITCH)          // 7680 bf16 = 15360 B
// 4 buffers: group g uses buffers {2g, 2g+1}
#define C_OFF (4 * BUF_ELEMS * 2)        // 61440 B; f32 C[2][2][1024] = 16384 B
#define SMEM_BYTES (C_OFF + 16384)       // 77824 B

// ---------------------------------------------------------------------------
// Device-global scratch (no cudaMalloc allowed)
// ---------------------------------------------------------------------------
__device__ float g_uu[K_DIM];
__device__ float g_ua[K_DIM];
__device__ float g_a2[K_DIM];
__device__ float g_vv[B_DIM];
__device__ __nv_bfloat16 g_ph[K_DIM * D_DIM];
__device__ __nv_bfloat16 g_pl[K_DIM * D_DIM];
__device__ __nv_bfloat16 g_ah[K_DIM * D_DIM];
__device__ __nv_bfloat16 g_al[K_DIM * D_DIM];
__device__ __nv_bfloat16 g_xh[B_DIM * D_DIM];
__device__ __nv_bfloat16 g_xl[B_DIM * D_DIM];

struct __align__(8) bh4 { __nv_bfloat162 a, b; };

__device__ __forceinline__ void split4(float4 v, __nv_bfloat16* hi,
                                       __nv_bfloat16* lo, int idx) {
    __nv_bfloat16 h0 = __float2bfloat16_rn(v.x);
    __nv_bfloat16 h1 = __float2bfloat16_rn(v.y);
    __nv_bfloat16 h2 = __float2bfloat16_rn(v.z);
    __nv_bfloat16 h3 = __float2bfloat16_rn(v.w);
    bh4 H; H.a = __nv_bfloat162(h0, h1); H.b = __nv_bfloat162(h2, h3);
    *(bh4*)(hi + idx) = H;
    bh4 L;
    L.a = __nv_bfloat162(__float2bfloat16_rn(v.x - __bfloat162float(h0)),
                         __float2bfloat16_rn(v.y - __bfloat162float(h1)));
    L.b = __nv_bfloat162(__float2bfloat16_rn(v.z - __bfloat162float(h2)),
                         __float2bfloat16_rn(v.w - __bfloat162float(h3)));
    *(bh4*)(lo + idx) = L;
}

// ---------------------------------------------------------------------------
// Kernel 1: per-row stats (fp32) + bf16 hi/lo split of p, a, x.
// ---------------------------------------------------------------------------
__global__ void stats_split_kernel(const float* __restrict__ inp,
                                   const float* __restrict__ p,
                                   const float* __restrict__ a) {
    int warp = (blockIdx.x * blockDim.x + threadIdx.x) >> 5;
    int lane = threadIdx.x & 31;

    if (warp < K_DIM) {
        const float4* pr = (const float4*)(p + warp * D_DIM);
        const float4* ar = (const float4*)(a + warp * D_DIM);
        float pp = 0.f, pa = 0.f, aa = 0.f;
#pragma unroll
        for (int i = 0; i < D_DIM / 128; i++) {
            float4 pv = pr[lane + i * 32];
            float4 av = ar[lane + i * 32];
            pp += pv.x * pv.x + pv.y * pv.y + pv.z * pv.z + pv.w * pv.w;
            pa += pv.x * av.x + pv.y * av.y + pv.z * av.z + pv.w * av.w;
            aa += av.x * av.x + av.y * av.y + av.z * av.z + av.w * av.w;
            int idx = warp * D_DIM + (lane + i * 32) * 4;
            split4(pv, g_ph, g_pl, idx);
            split4(av, g_ah, g_al, idx);
        }
#pragma unroll
        for (int off = 16; off > 0; off >>= 1) {
            pp += __shfl_xor_sync(0xFFFFFFFFu, pp, off);
            pa += __shfl_xor_sync(0xFFFFFFFFu, pa, off);
            aa += __shfl_xor_sync(0xFFFFFFFFu, aa, off);
        }
        if (lane == 0) {
            g_uu[warp] = pp;
            g_ua[warp] = -pa;
            g_a2[warp] = aa;
        }
    } else if (warp < K_DIM + B_DIM) {
        int b = warp - K_DIM;
        const float4* xr = (const float4*)(inp + b * D_DIM);
        float vv = 0.f;
#pragma unroll
        for (int i = 0; i < D_DIM / 128; i++) {
            float4 xv = xr[lane + i * 32];
            vv += xv.x * xv.x + xv.y * xv.y + xv.z * xv.z + xv.w * xv.w;
            split4(xv, g_xh, g_xl, b * D_DIM + (lane + i * 32) * 4);
        }
#pragma unroll
        for (int off = 16; off > 0; off >>= 1)
            vv += __shfl_xor_sync(0xFFFFFFFFu, vv, off);
        if (lane == 0) g_vv[b] = vv;
    }
}

// cp.async helpers
__device__ __forceinline__ void cp16(void* dst, const void* src) {
    unsigned saddr = (unsigned)__cvta_generic_to_shared(dst);
    asm volatile("cp.async.cg.shared.global [%0], [%1], 16;\n"
                 :: "r"(saddr), "l"(src));
}
__device__ __forceinline__ void cp_commit() {
    asm volatile("cp.async.commit_group;\n" ::: "memory");
}
__device__ __forceinline__ void cp_wait1() {
    asm volatile("cp.async.wait_group 1;\n" ::: "memory");
}
__device__ __forceinline__ void cp_wait0() {
    asm volatile("cp.async.wait_group 0;\n" ::: "memory");
}
// named barrier for one warpgroup (256 threads)
__device__ __forceinline__ void gbar(int id) {
    asm volatile("bar.sync %0, 256;" :: "r"(id) : "memory");
}

// ---------------------------------------------------------------------------
// Kernel 2: bf16 WMMA dual GEMM (3-term fp32-emulation) + MLR epilogue.
// Grid (K/BN, B/BM) = (128, 2) = 256 blocks, 512 threads (16 warps).
// Intra-block split-D: warpgroup g (threads 256g..256g+255) accumulates the
// SAME 64x16 output tile over d in [256g, 256g+256), with its own
// double-buffered cp.async stream and named-barrier stage sync (id g+1).
// Within a group: warps 0-3 -> P-GEMM rows [16w,16w+16), warps 4-7 -> A-GEMM.
// Partials meet in smem C[2][2][1024]; epilogue sums groups and applies asinh.
// ---------------------------------------------------------------------------
__global__ __launch_bounds__(THREADS, 2)
void hyper_logits_wmma(float* __restrict__ out) {
    extern __shared__ __align__(16) __nv_bfloat16 smb[];
    float* C = (float*)((char*)smb + C_OFF);    // [2 groups][2 mats][1024]

    const int tid = threadIdx.x;
    const int grp = tid >> 8;           // warpgroup 0/1
    const int gt = tid & 255;           // id within group
    const int warp = gt >> 5;           // 0..7 within group
    const int mat = warp >> 2;          // 0: P-GEMM, 1: A-GEMM
    const int wb = warp & 3;            // b-row group (16 rows)
    const int kbase = blockIdx.x * BN;
    const int bbase = blockIdx.y * BM;
    const int dbase = grp * GD;

    // ---- stage copy: 3 cp16 per thread (group-local) ----
    auto copy_stage = [&](int s) {
        __nv_bfloat16* buf = smb + (grp * 2 + (s & 1)) * BUF_ELEMS;
        const int d0 = dbase + s * DCW;
        {   // X hi + lo: 64 rows x 4 16B-chunks
            int row = gt >> 2, c8 = (gt & 3) * 8;
            size_t g = (size_t)(bbase + row) * D_DIM + d0 + c8;
            int so = row * PITCH + c8;
            cp16(buf + XH_B + so, g_xh + g);
            cp16(buf + XL_B + so, g_xl + g);
        }
        {   // weights: 4 arrays x 16 rows x 2 chunks... (64 cp16 per array)
            int arr = gt >> 6, r = gt & 63;
            int row = r >> 2, c8 = (r & 3) * 8;
            size_t g = (size_t)(kbase + row) * D_DIM + d0 + c8;
            int so = row * PITCH + c8;
            const __nv_bfloat16* src =
                (arr == 0) ? g_ph : (arr == 1) ? g_pl : (arr == 2) ? g_ah : g_al;
            int dstb = (arr == 0) ? PH_B : (arr == 1) ? PL_B
                     : (arr == 2) ? AH_B : AL_B;
            cp16(buf + dstb + so, src + g);
        }
    };

    wmma::fragment<wmma::accumulator, 16, 16, 16, float> acc;
    wmma::fill_fragment(acc, 0.0f);

    copy_stage(0);
    cp_commit();

    for (int t = 0; t < NST; t++) {
        if (t + 1 < NST) {
            copy_stage(t + 1);
            cp_commit();
            cp_wait1();
        } else {
            cp_wait0();
        }
        gbar(grp + 1);

        const __nv_bfloat16* buf = smb + (grp * 2 + (t & 1)) * BUF_ELEMS;
        const __nv_bfloat16* xh = buf + XH_B + wb * 16 * PITCH;
        const __nv_bfloat16* xl = buf + XL_B + wb * 16 * PITCH;
        const __nv_bfloat16* bh = buf + (mat ? AH_B : PH_B);
        const __nv_bfloat16* bl = buf + (mat ? AL_B : PL_B);

#pragma unroll
        for (int cc = 0; cc < DCW / 16; cc++) {
            const int dcol = cc * 16;
            wmma::fragment<wmma::matrix_a, 16, 16, 16, __nv_bfloat16,
                           wmma::row_major> aH, aL;
            wmma::fragment<wmma::matrix_b, 16, 16, 16, __nv_bfloat16,
                           wmma::col_major> fBH, fBL;
            wmma::load_matrix_sync(aH, xh + dcol, PITCH);
            wmma::load_matrix_sync(aL, xl + dcol, PITCH);
            wmma::load_matrix_sync(fBH, bh + dcol, PITCH);
            wmma::load_matrix_sync(fBL, bl + dcol, PITCH);

            wmma::mma_sync(acc, aH, fBH, acc);
            wmma::mma_sync(acc, aH, fBL, acc);
            wmma::mma_sync(acc, aL, fBH, acc);
        }
        gbar(grp + 1);
    }

    // ---- dump partial accumulators: C[grp][mat][wb*256 ...] ----
    wmma::store_matrix_sync(C + (grp * 2 + mat) * 1024 + wb * 256, acc, 16,
                            wmma::mem_row_major);
    __syncthreads();

    // ---- epilogue: 1024 logits, 2 per thread; sum the two D-halves ----
#pragma unroll
    for (int i = 0; i < 2; i++) {
        int idx = tid + THREADS * i;                // 0..1023
        int r = idx >> 4;                           // local b row 0..63
        int c = idx & 15;                           // local k col
        const int b = bbase + r;
        const int k = kbase + c;

        float xp = C[idx] + C[2048 + idx];          // grp0 P + grp1 P
        float xa = C[1024 + idx] + C[3072 + idx];   // grp0 A + grp1 A

        const float uu = g_uu[k];
        const float ua = g_ua[k];
        const float an = sqrtf(g_a2[k]);
        const float coef = 2.0f / (1.0f - uu) * an;
        const float beta = 1.0f - uu;
        const float vv = g_vv[b];

        float uv = -xp;                             // <u,x> = -<p,x>
        float alpha = 1.0f + 2.0f * uv + vv;
        float den   = 1.0f + 2.0f * uv + uu * vv;
        float inv   = 1.0f / den;
        float wa = (alpha * ua + beta * xa) * inv;
        float ww = (alpha * alpha * uu + 2.0f * alpha * beta * uv
                    + beta * beta * vv) * (inv * inv);
        out[b * K_DIM + k] = coef * asinhf(2.0f * wa / (an * (1.0f - ww)));
    }
}

// ---------------------------------------------------------------------------
extern "C" void kernel_launch(void* const* d_in, const int* in_sizes, int n_in,
                              void* d_out, int out_size) {
    const float* inp = (const float*)d_in[0];   // [B, D]
    const float* p   = (const float*)d_in[1];   // [K, D]
    const float* a   = (const float*)d_in[2];   // [K, D]
    float* out = (float*)d_out;                 // [B, K]

    static bool attr_set = false;
    if (!attr_set) {
        cudaFuncSetAttribute(hyper_logits_wmma,
                             cudaFuncAttributeMaxDynamicSharedMemorySize,
                             SMEM_BYTES);
        attr_set = true;
    }

    int nwarps = K_DIM + B_DIM;
    int blocks1 = (nwarps * 32 + 255) / 256;
    stats_split_kernel<<<blocks1, 256>>>(inp, p, a);

    dim3 grid(K_DIM / BN, B_DIM / BM);   // (128, 2) = 256 blocks
    hyper_logits_wmma<<<grid, THREADS, SMEM_BYTES>>>(out);
}